// round 5
// baseline (speedup 1.0000x reference)
#include <cuda_runtime.h>
#include <math.h>

#define Bsz 4
#define Cch 192
#define Hh 56
#define Ww 56
#define HW (Hh*Ww)

// scratch (static device globals; no allocation)
__device__ float g_xt  [Bsz*HW*Cch];  // x transposed to [b][n][c]  (NHWC)
__device__ float g_att [Bsz*HW*Cch];  // attention output, h-shift part
__device__ float g_attw[Bsz*HW*Cch];  // attention output, w-shift part
__device__ float g_sc  [Bsz*HW*32];   // scores, padded row of 32 (cols 0..26 used)

// ---------------------------------------------------------------------------
// Kernel 1: NCHW -> NHWC transpose
// ---------------------------------------------------------------------------
__global__ __launch_bounds__(256) void transpose_k(const float* __restrict__ x)
{
    __shared__ float tile[32][33];
    const int n0 = blockIdx.x << 5;
    const int c0 = blockIdx.y << 5;
    const int b  = blockIdx.z;
    const int tx = threadIdx.x, ty = threadIdx.y;
    const float* xb = x + (size_t)b * Cch * HW;
#pragma unroll
    for (int i = 0; i < 4; i++)
        tile[ty + i*8][tx] = xb[(size_t)(c0 + ty + i*8) * HW + n0 + tx];
    __syncthreads();
    float* dst = g_xt + (size_t)b * HW * Cch;
#pragma unroll
    for (int i = 0; i < 4; i++)
        dst[(size_t)(n0 + ty + i*8) * Cch + c0 + tx] = tile[tx][ty + i*8];
}

// ---------------------------------------------------------------------------
// tanh: (1-e)/(1+e) = 2*rcp(1+e) - 1,  e = 2^(-2a*log2e).  6 instr / 2 MUFU.
// ---------------------------------------------------------------------------
__device__ __forceinline__ float fast_tanh(float p)
{
    float z = fabsf(p) * -2.885390082f;       // -2a*log2(e)
    float e; asm("ex2.approx.f32 %0, %1;" : "=f"(e) : "f"(z));
    float d = 1.0f + e;
    float r; asm("rcp.approx.f32 %0, %1;" : "=f"(r) : "f"(d));
    float t = fmaf(2.0f, r, -1.0f);
    return copysignf(t, p);
}

// ---------------------------------------------------------------------------
// Kernel 2: ring pair-score kernel. Block = one 14-ring (h-ring mode0, w-ring
// mode1). Each unordered pair (i,j) serves two (position,shift) score entries.
// ---------------------------------------------------------------------------
#define TS_STRIDE 193   // bank(p,c) = (p+c)%32 -> conflict-free rows

template<int LO, int HI, int MODE>
__device__ __forceinline__ void score_compute(const float* sxr, const float* xr,
                                              float* ts, int c)
{
    int p = 0;
#pragma unroll
    for (int i = 0; i < 14; i++)
#pragma unroll
        for (int j = (MODE ? i + 1 : i); j < 14; j++) {
            if (p >= LO && p < HI)
                ts[(p - LO)*TS_STRIDE + c] = fast_tanh(sxr[i] * xr[j]);
            p++;
        }
}

__device__ __forceinline__ void reduce_rows(const float* ts, float* redS,
                                            int c, int nrows, int base)
{
    if (c < nrows) {
        const float* row = ts + c*TS_STRIDE;
        float s0=0.f, s1=0.f, s2=0.f, s3=0.f;
#pragma unroll 8
        for (int cc = 0; cc < 192; cc += 4) {
            s0 += row[cc]; s1 += row[cc+1]; s2 += row[cc+2]; s3 += row[cc+3];
        }
        redS[base + c] = (s0 + s1) + (s2 + s3);
    }
}

__global__ __launch_bounds__(192) void score_k()
{
    __shared__ float ts[53 * TS_STRIDE];   // 40.9KB
    __shared__ float redS[105];
    const int x = blockIdx.x;              // w (mode0) or h (mode1)
    const int r = blockIdx.y;              // residue 0..3
    const int b = blockIdx.z >> 1, mode = blockIdx.z & 1;
    const int c = threadIdx.x;
    const float* base = g_xt + (size_t)b * HW * Cch;

    float xr[14], sxr[14];
#pragma unroll
    for (int a = 0; a < 14; a++) {
        int n = mode ? (x*Ww + r + 4*a) : ((r + 4*a)*Ww + x);
        xr[a]  = base[n*Cch + c];
        sxr[a] = xr[a] * 0.19245008972987526f;   // 27^-0.5
    }
    const int NP = mode ? 91 : 105;

    if (mode == 0) score_compute<0,53,0>(sxr, xr, ts, c);
    else           score_compute<0,53,1>(sxr, xr, ts, c);
    __syncthreads();
    reduce_rows(ts, redS, c, 53, 0);
    __syncthreads();
    if (mode == 0) score_compute<53,105,0>(sxr, xr, ts, c);
    else           score_compute<53,91,1>(sxr, xr, ts, c);
    __syncthreads();
    reduce_rows(ts, redS, c, NP - 53, 53);
    __syncthreads();

    float* scb = g_sc + (size_t)b * HW * 32;
    if (mode == 0) {
        for (int e = c; e < 196; e += 192) {        // 14 pos x 14 h-shifts
            int a = e / 14, k = e % 14;
            int j = a - k; if (j < 0) j += 14;
            int lo = min(a, j), hi = max(a, j);
            int id = lo*14 - (lo*(lo-1))/2 + (hi - lo);
            int n = (r + 4*a)*Ww + x;
            scb[n*32 + k] = redS[id];
        }
    } else {
        for (int e = c; e < 182; e += 192) {        // 14 pos x 13 w-shifts
            int a = e / 13, m = e % 13 + 1;
            int j = a - m; if (j < 0) j += 14;
            int lo = min(a, j), hi = max(a, j);
            int id = lo*13 - (lo*(lo-1))/2 + (hi - lo - 1);
            int n = x*Ww + r + 4*a;
            scb[n*32 + 13 + m] = redS[id];
        }
    }
}

// ---------------------------------------------------------------------------
// Kernel 3: ring weighted-sum, BOTH modes in one launch (independent outputs:
// mode0 -> g_att (h-part), mode1 -> g_attw (w-part); gemm adds them).
// ---------------------------------------------------------------------------
__global__ __launch_bounds__(192) void sum_k()
{
    __shared__ float wgt[14*14];
    const int x = blockIdx.x, r = blockIdx.y;
    const int b = blockIdx.z >> 1, mode = blockIdx.z & 1;
    const int c = threadIdx.x;
    const float* base = g_xt + (size_t)b * HW * Cch;
    float* attb = (mode ? g_attw : g_att) + (size_t)b * HW * Cch;
    const float* scb = g_sc + (size_t)b * HW * 32;

    if (c < 14) {                                // thread = one ring position
        int n = mode ? (x*Ww + r + 4*c) : ((r + 4*c)*Ww + x);
        const float* srow = scb + n*32;
        float s[27], mx = -1e30f;
#pragma unroll
        for (int k = 0; k < 27; k++) { s[k] = srow[k]; mx = fmaxf(mx, s[k]); }
        float tot = 0.f;
#pragma unroll
        for (int k = 0; k < 27; k++) { s[k] = __expf(s[k] - mx); tot += s[k]; }
        float inv = __fdividef(1.f, tot);
        if (mode == 0) {
#pragma unroll
            for (int k = 0; k < 14; k++) wgt[c*14 + k] = s[k] * inv;
        } else {
#pragma unroll
            for (int m = 1; m < 14; m++) wgt[c*14 + m-1] = s[13 + m] * inv;
        }
    }
    __syncthreads();

    float xr[14];
#pragma unroll
    for (int a = 0; a < 14; a++) {
        int n = mode ? (x*Ww + r + 4*a) : ((r + 4*a)*Ww + x);
        xr[a] = base[n*Cch + c];
    }
#pragma unroll
    for (int a = 0; a < 14; a++) {
        int n = mode ? (x*Ww + r + 4*a) : ((r + 4*a)*Ww + x);
        float o = 0.f;
        if (mode == 0) {
#pragma unroll
            for (int k = 0; k < 14; k++) {
                int j = (a - k + 14) % 14;
                o = fmaf(wgt[a*14 + k], xr[j], o);
            }
        } else {
#pragma unroll
            for (int m = 1; m < 14; m++) {
                int j = (a - m + 14) % 14;
                o = fmaf(wgt[a*14 + m-1], xr[j], o);
            }
        }
        attb[n*Cch + c] = o;
    }
}

// ---------------------------------------------------------------------------
// Kernel 4: GEMM (M=192, N=3136/b, K=384) + bias + BN + GELU, FFMA2 inner
// loop, software-pipelined (next tile in regs while computing current).
// Second K-half loads att_h + att_w and adds.
// ---------------------------------------------------------------------------
#define BN 32
#define BK 32
#define WS_STRIDE 194
#define CS2 66

#define FFMA2(d, a, b) asm("fma.rn.f32x2 %0, %1, %2, %0;" : "+l"(d) : "l"(a), "l"(b))

__global__ __launch_bounds__(256, 3) void gemm_k(
    const float* __restrict__ cw,
    const float* __restrict__ bias,
    const float* __restrict__ gamma,
    const float* __restrict__ beta,
    const float* __restrict__ mean,
    const float* __restrict__ var,
    float* __restrict__ out)
{
    __shared__ float wS[BK * WS_STRIDE];    // [k][o]
    __shared__ float catS[BK * CS2];        // [k][n] duplicated pairs
    const int b  = blockIdx.y;
    const int n0 = blockIdx.x * BN;
    const int t  = threadIdx.x;
    const int tn = t & 15;                  // 16 n-groups of 2
    const int tm = t >> 4;                  // 16 o-groups of 12

    unsigned long long acc[6][2];
#pragma unroll
    for (int p = 0; p < 6; p++)
#pragma unroll
        for (int nn = 0; nn < 2; nn++) acc[p][nn] = 0ULL;

    const float* xb = g_xt   + (size_t)b * HW * Cch;
    const float* ah = g_att  + (size_t)b * HW * Cch;
    const float* aw = g_attw + (size_t)b * HW * Cch;

    // per-thread load coordinates
    const int lc  = t & 31, lj = t >> 5;        // cat element (per s: +8 j)
    const int lc4 = (t & 7) * 4, lo = t >> 3;   // weight float4 (per s: +32 o)

    float  cv[4];
    float4 wv[6];
#define LOAD_TILE(KC) do {                                                   \
        const int cb_ = ((KC) < Cch) ? (KC) : ((KC) - Cch);                  \
        if ((KC) < Cch) {                                                    \
            _Pragma("unroll")                                                \
            for (int s = 0; s < 4; s++)                                      \
                cv[s] = xb[(size_t)(n0 + lj + 8*s)*Cch + cb_ + lc];          \
        } else {                                                             \
            _Pragma("unroll")                                                \
            for (int s = 0; s < 4; s++) {                                    \
                size_t ix = (size_t)(n0 + lj + 8*s)*Cch + cb_ + lc;          \
                cv[s] = ah[ix] + aw[ix];                                     \
            }                                                                \
        }                                                                    \
        _Pragma("unroll")                                                    \
        for (int s = 0; s < 6; s++)                                          \
            wv[s] = *reinterpret_cast<const float4*>(                        \
                        &cw[(lo + 32*s)*384 + (KC) + lc4]);                  \
    } while (0)

    LOAD_TILE(0);
#pragma unroll 1
    for (int it = 0; it < 12; it++) {
        __syncthreads();
#pragma unroll
        for (int s = 0; s < 4; s++) {
            float v = cv[s];
            *reinterpret_cast<float2*>(&catS[lc*CS2 + 2*(lj + 8*s)]) =
                make_float2(v, v);
        }
#pragma unroll
        for (int s = 0; s < 6; s++) {
            int o = lo + 32*s;
            wS[(lc4+0)*WS_STRIDE + o] = wv[s].x;
            wS[(lc4+1)*WS_STRIDE + o] = wv[s].y;
            wS[(lc4+2)*WS_STRIDE + o] = wv[s].z;
            wS[(lc4+3)*WS_STRIDE + o] = wv[s].w;
        }
        __syncthreads();
        if (it < 11) LOAD_TILE((it + 1) * BK);
#pragma unroll
        for (int k = 0; k < BK; k++) {
            unsigned long long a[6], bb[2];
#pragma unroll
            for (int p = 0; p < 6; p++)
                a[p] = *reinterpret_cast<const unsigned long long*>(
                           &wS[k*WS_STRIDE + tm*12 + 2*p]);
            bb[0] = *reinterpret_cast<const unsigned long long*>(&catS[k*CS2 + 4*tn]);
            bb[1] = *reinterpret_cast<const unsigned long long*>(&catS[k*CS2 + 4*tn + 2]);
#pragma unroll
            for (int p = 0; p < 6; p++)
#pragma unroll
                for (int nn = 0; nn < 2; nn++)
                    FFMA2(acc[p][nn], a[p], bb[nn]);
        }
    }

#pragma unroll
    for (int p = 0; p < 6; p++) {
        float yv[2][2];
#pragma unroll
        for (int nn = 0; nn < 2; nn++) {
            unsigned long long v = acc[p][nn];
            yv[0][nn] = __uint_as_float((unsigned)v);
            yv[1][nn] = __uint_as_float((unsigned)(v >> 32));
        }
#pragma unroll
        for (int q = 0; q < 2; q++) {
            int o = tm*12 + 2*p + q;
            float bi  = bias[o];
            float inv = gamma[o] * rsqrtf(var[o] + 1e-5f);
            float mu  = mean[o], bt = beta[o];
            float2 rr;
#pragma unroll
            for (int nn = 0; nn < 2; nn++) {
                float y = (yv[q][nn] + bi - mu) * inv + bt;
                ((float*)&rr)[nn] = 0.5f * y * (1.0f + erff(y * 0.70710678118654752f));
            }
            *reinterpret_cast<float2*>(
                &out[(size_t)(b*Cch + o)*HW + n0 + tn*2]) = rr;
        }
    }
}

// ---------------------------------------------------------------------------
extern "C" void kernel_launch(void* const* d_in, const int* in_sizes, int n_in,
                              void* d_out, int out_size)
{
    const float* x     = (const float*)d_in[0];
    const float* cw    = (const float*)d_in[1];
    const float* cb    = (const float*)d_in[2];
    const float* gamma = (const float*)d_in[3];
    const float* beta  = (const float*)d_in[4];
    const float* mean  = (const float*)d_in[5];
    const float* var   = (const float*)d_in[6];
    float* out = (float*)d_out;

    transpose_k<<<dim3(HW/32, Cch/32, Bsz), dim3(32, 8)>>>(x);
    score_k<<<dim3(56, 4, 2*Bsz), 192>>>();
    sum_k<<<dim3(56, 4, 2*Bsz), 192>>>();
    gemm_k<<<dim3(HW/BN, Bsz), 256>>>(cw, cb, gamma, beta, mean, var, out);
}